// round 4
// baseline (speedup 1.0000x reference)
#include <cuda_runtime.h>
#include <math.h>

#define TMAX 2048
#define S 193          // stride of 192x192 bordered workspace (odd -> conflict-free columns)
#define S2 65          // stride of persistent 64x64 blocks
#define NTHREADS 256
#define LOG2PI 1.8378770664093453f

// ---------------- device scratch (no allocations allowed) ----------------
__device__ float gSaa[64 * 64];
__device__ float gSabT[64 * 64];
__device__ float gSbb[64 * 64];
__device__ float gMuT[TMAX * 64];
__device__ float gIvdT[TMAX * 64];
__device__ float gFvar[64 * 64];
__device__ float gFmu[64];
__device__ float gFscore;

// ---------------- precompute transition blocks ----------------
// trans_var = trans_cho^T @ trans_cho (128x128).
// gSaa[r][c]  = tv[r][c]        (r,c < 64)
// gSabT[r][c] = tv[c][64+r]     (= Sab^T)
// gSbb[r][c]  = tv[64+r][64+c]
__global__ void __launch_bounds__(256) prek_kernel(const float* __restrict__ tcho) {
    extern __shared__ float s[];   // 128*128 floats
    int tid = threadIdx.x;
    for (int i = tid; i < 128 * 128; i += 256) s[i] = tcho[i];
    __syncthreads();
    int which = blockIdx.x;
    int r0 = (tid >> 4) << 2, c0 = (tid & 15) << 2;
    int ra = (which == 0) ? r0 : (64 + r0);
    int cb = (which == 2) ? (64 + c0) : c0;
    float acc[4][4];
#pragma unroll
    for (int q = 0; q < 4; q++)
#pragma unroll
        for (int w = 0; w < 4; w++) acc[q][w] = 0.f;
    for (int k = 0; k < 128; ++k) {
        const float* row = s + (k << 7);
        float a[4], b[4];
#pragma unroll
        for (int q = 0; q < 4; q++) a[q] = row[ra + q];
#pragma unroll
        for (int w = 0; w < 4; w++) b[w] = row[cb + w];
#pragma unroll
        for (int q = 0; q < 4; q++)
#pragma unroll
            for (int w = 0; w < 4; w++) acc[q][w] += a[q] * b[w];
    }
    float* dst = (which == 0) ? gSaa : ((which == 1) ? gSabT : gSbb);
#pragma unroll
    for (int q = 0; q < 4; q++)
#pragma unroll
        for (int w = 0; w < 4; w++) dst[(r0 + q) * 64 + c0 + w] = acc[q][w];
}

// ---------------- gather token embeddings ----------------
__global__ void gather_kernel(const int* __restrict__ sent,
                              const float* __restrict__ memb,
                              const float* __restrict__ cemb, int n) {
    int t = blockIdx.x;
    if (t >= n) return;
    int c = threadIdx.x;   // 64 threads
    int tok = sent[t];
    gMuT[t * 64 + c] = memb[tok * 64 + c];
    float ch = cemb[tok * 64 + c];
    gIvdT[t * 64 + c] = ch * ch;
}

// ---------------- sequential scan: bordered 192x192 factorization per step ----------------
__global__ void __launch_bounds__(NTHREADS, 1) scan_kernel(const float* __restrict__ tmu,
                                                           const int* __restrict__ slenp) {
    extern __shared__ float sm[];
    float* M    = sm;                       // 192*193
    float* sSaa = sm + 192 * S;             // 64*65 each
    float* sSab = sSaa + 64 * S2;
    float* sSbb = sSab + 64 * S2;
    float* v    = sSbb + 64 * S2;           // 192
    float* sMu  = v + 192;                  // 64
    float* sMuA = sMu + 64;
    float* sMuB = sMuA + 64;
    float* sIm  = sMuB + 64;
    float* sIvd = sIm + 64;
    float* sInv = sIvd + 64;                // 128
    float* sRed = sInv + 128;               // 8
    float* sSc  = sRed + 8;                 // 1

    int tid = threadIdx.x;
    int slen = slenp[0];
    if (slen > TMAX) slen = TMAX;
    if (slen < 0) slen = 0;

    for (int idx = tid; idx < 64 * 64; idx += NTHREADS) {
        int r = idx >> 6, c = idx & 63;
        sSaa[r * S2 + c] = gSaa[idx];
        sSab[r * S2 + c] = gSabT[idx];
        sSbb[r * S2 + c] = gSbb[idx];
    }
    if (tid < 64) {
        sMuA[tid] = tmu[tid];
        sMuB[tid] = tmu[64 + tid];
        sIm[tid] = 0.f;     // init iteration: mu1 = 0
        sIvd[tid] = 1.f;    // init iteration: var1 = I
    }
    if (tid == 0) sSc[0] = 0.f;
    __syncthreads();

    float pim = 0.f, pivd = 0.f;
    for (int t = -1; t < slen; ++t) {
        // prefetch token t+1 into registers (consumed at end of this iteration)
        if (t + 1 < slen) {
            if (tid < 64) pim = gMuT[(t + 1) * 64 + tid];
            else if (tid < 128) pivd = gIvdT[(t + 1) * 64 + (tid - 64)];
        }
        int jstart = (t < 0) ? 64 : 0;

        // ---- phase A: capture previous state (var_t -> block(0,0), mu_t -> sMu) ----
        if (t >= 0) {
            for (int idx = tid; idx < 64 * 64; idx += NTHREADS) {
                int i = idx >> 6, k = idx & 63;
                if (k <= i) {
                    float val = M[(128 + i) * S + 128 + k];
                    if (k == i) val += sIvd[i];
                    M[i * S + k] = val;       // vs = V + D (lower)
                }
            }
            if (tid < 64) sMu[tid] = v[128 + tid];
        }
        __syncthreads();

        // ---- phase B: rebuild remaining blocks and RHS ----
        for (int idx = tid; idx < 64 * 64; idx += NTHREADS) {
            int i = idx >> 6, k = idx & 63;
            M[(64 + i) * S + k] = (i == k) ? sIvd[i] : 0.f;                    // block(1,0) = D
            if (k <= i) M[(64 + i) * S + 64 + k] =
                sSaa[i * S2 + k] + ((i == k) ? sIvd[i] : 0.f);                 // block(1,1) = Saa + D
            M[(128 + i) * S + 64 + k] = sSab[i * S2 + k];                      // block(2,1) = Sab^T
            if (k <= i) M[(128 + i) * S + 128 + k] = sSbb[i * S2 + k];         // block(2,2) = Sbb
        }
        if (tid < 64) {
            v[tid]       = sMu[tid]  - sIm[tid];   // mu_prev - im
            v[64 + tid]  = sMuA[tid] - sIm[tid];   // mu_a - im
            v[128 + tid] = sMuB[tid];              // mu_b
        }
        __syncthreads();

        // ---- factorization: eliminate columns jstart..127 (panelled, B=16) ----
        for (int p = (jstart >> 4); p < 8; ++p) {
            int c0 = p << 4;
            int rlim = (c0 < 64) ? 128 : 192;   // rows >=128 untouched while j<64 (block(2,0)=0)

            // panel factorization: 1 barrier per column
            for (int jj = 0; jj < 16; ++jj) {
                int j = c0 + jj;
                float piv = M[j * S + j];
                float rp = __frcp_rn(piv);
                if (tid == 0) sInv[j] = rp;
                int k = j + 1 + (tid & 15);
                if (k < c0 + 16) {
                    float mk = M[k * S + j] * rp;
                    for (int i = k + (tid >> 4); i < rlim; i += 16)
                        M[i * S + k] -= M[i * S + j] * mk;
                }
                int iv = j + 1 + tid;
                if (iv < rlim) v[iv] -= M[iv * S + j] * (v[j] * rp);
                __syncthreads();
            }

            // rank-16 trailing update, register-tiled 4x4, lower-triangle tiles only
            int t0 = c0 + 16;
            int n = rlim - t0;                    // always a multiple of 16
            int ntile = n >> 2;
            int ntri = (ntile * (ntile + 1)) >> 1;
            for (int m = tid; m < ntri; m += NTHREADS) {
                int ti = (int)((sqrtf(8.f * (float)m + 1.f) - 1.f) * 0.5f);
                while ((ti + 1) * (ti + 2) / 2 <= m) ++ti;
                while (ti * (ti + 1) / 2 > m) --ti;
                int tk = m - ((ti * (ti + 1)) >> 1);
                int i0 = t0 + (ti << 2), k0 = t0 + (tk << 2);
                float acc[4][4];
#pragma unroll
                for (int q = 0; q < 4; q++)
#pragma unroll
                    for (int w = 0; w < 4; w++) acc[q][w] = M[(i0 + q) * S + k0 + w];
#pragma unroll
                for (int jj = 0; jj < 16; ++jj) {
                    int j = c0 + jj;
                    float ivj = sInv[j];
                    float a[4], b[4];
#pragma unroll
                    for (int q = 0; q < 4; q++) a[q] = M[(i0 + q) * S + j];
#pragma unroll
                    for (int w = 0; w < 4; w++) b[w] = M[(k0 + w) * S + j] * ivj;
#pragma unroll
                    for (int q = 0; q < 4; q++)
#pragma unroll
                        for (int w = 0; w < 4; w++) acc[q][w] -= a[q] * b[w];
                }
#pragma unroll
                for (int q = 0; q < 4; q++)
#pragma unroll
                    for (int w = 0; w < 4; w++) M[(i0 + q) * S + k0 + w] = acc[q][w];
            }
            __syncthreads();
        }

        // ---- score reduction: sum over eliminated pivots of v^2/piv + log(piv) ----
        float my = 0.f;
        if (tid >= jstart && tid < 128) {
            float ivj = sInv[tid];
            float z = v[tid];
            my = z * z * ivj - logf(ivj);   // log(piv) = -log(inv)
        }
        for (int o = 16; o > 0; o >>= 1) my += __shfl_down_sync(0xffffffffu, my, o);
        if ((tid & 31) == 0 && tid < 128) sRed[tid >> 5] = my;

        // stage next token's im/ivd (last read of current ones was phase B)
        if (t + 1 < slen) {
            if (tid < 64) sIm[tid] = pim;
            else if (tid < 128) sIvd[tid - 64] = pivd;
        }
        __syncthreads();
        if (tid == 0) {
            float tot = sRed[0] + sRed[1] + sRed[2] + sRed[3];
            float cnt = (t < 0) ? 64.f : 128.f;
            sSc[0] += -0.5f * (cnt * LOG2PI + tot);
        }
        __syncthreads();
    }

    // ---- export final state ----
    for (int idx = tid; idx < 64 * 64; idx += NTHREADS) {
        int i = idx >> 6, k = idx & 63;
        gFvar[idx] = (k <= i) ? M[(128 + i) * S + 128 + k] : 0.f;
    }
    if (tid < 64) gFmu[tid] = v[128 + tid];
    if (tid == 0) gFscore = sSc[0];
}

// ---------------- decode: 50 independent 64x64 Cholesky scores ----------------
__global__ void __launch_bounds__(64) decode_kernel(const float* __restrict__ omu,
                                                    const float* __restrict__ ocho,
                                                    float* __restrict__ out, int nlab) {
    __shared__ float A[64 * S2];
    __shared__ float z[64];
    __shared__ float red[2];
    int l = blockIdx.x;
    if (l >= nlab) return;
    int i = threadIdx.x;   // 64 threads, thread i owns row i
    for (int k = 0; k <= i; ++k) A[i * S2 + k] = gFvar[i * 64 + k];
    float oc = ocho[l * 64 + i];
    A[i * S2 + i] += oc * oc;
    z[i] = gFmu[i] - omu[l * 64 + i];
    __syncthreads();
    float acc = 0.f;
    for (int j = 0; j < 64; ++j) {
        float piv = A[j * S2 + j];
        float rp = __frcp_rn(piv);
        if (i == j) acc = logf(piv) + z[j] * z[j] * rp;
        if (i > j) {
            float mij = A[i * S2 + j];
            z[i] -= mij * (z[j] * rp);
            float mjr = mij * rp;
            for (int k = j + 1; k <= i; ++k) A[i * S2 + k] -= mjr * A[k * S2 + j];
        }
        __syncthreads();
    }
    for (int o = 16; o > 0; o >>= 1) acc += __shfl_down_sync(0xffffffffu, acc, o);
    if ((i & 31) == 0) red[i >> 5] = acc;
    __syncthreads();
    if (i == 0) out[l] = gFscore - 0.5f * (64.f * LOG2PI + red[0] + red[1]);
}

// ---------------- launch ----------------
static const int SCAN_SMEM_BYTES = (192 * S + 3 * 64 * S2 + 192 + 5 * 64 + 128 + 8 + 4) * 4;

extern "C" void kernel_launch(void* const* d_in, const int* in_sizes, int n_in,
                              void* d_out, int out_size) {
    const int*   sent = (const int*)d_in[0];
    const int*   slen = (const int*)d_in[1];
    const float* memb = (const float*)d_in[2];
    const float* cemb = (const float*)d_in[3];
    const float* tmu  = (const float*)d_in[4];
    const float* tcho = (const float*)d_in[5];
    const float* omu  = (const float*)d_in[6];
    const float* ocho = (const float*)d_in[7];
    float* out = (float*)d_out;

    int n = in_sizes[0];
    if (n > TMAX) n = TMAX;
    int nlab = out_size;
    if (nlab <= 0) nlab = in_sizes[6] / 64;

    cudaFuncSetAttribute(prek_kernel, cudaFuncAttributeMaxDynamicSharedMemorySize, 128 * 128 * 4);
    cudaFuncSetAttribute(scan_kernel, cudaFuncAttributeMaxDynamicSharedMemorySize, SCAN_SMEM_BYTES);

    prek_kernel<<<3, 256, 128 * 128 * 4>>>(tcho);
    gather_kernel<<<n, 64>>>(sent, memb, cemb, n);
    scan_kernel<<<1, NTHREADS, SCAN_SMEM_BYTES>>>(tmu, slen);
    decode_kernel<<<nlab, 64>>>(omu, ocho, out, nlab);
}

// round 7
// speedup vs baseline: 52.3222x; 52.3222x over previous
#include <cuda_runtime.h>
#include <math.h>

#define TMAX 2048
// element layout (floats): mu[0..127], logw at 128, pad to 136, Sigma 128x128
#define ELT 16520
#define MU_OFF 0
#define W_OFF 128
#define SIG_OFF 136
#define SS 65           // stride of 64x64 smem S block
#define SWD 132         // stride of 64x129 smem W block (mult of 4 -> float4 ok)
#define NT 256
#define LOG2PI 1.8378770664093453f

// ---------------- device scratch (static; no allocations) ----------------
__device__ float gTvar[128 * 128];
__device__ float gBufA[(size_t)TMAX * ELT];
__device__ float gBufB[(size_t)(TMAX / 2) * ELT];
__device__ float gEG[ELT];   // bare transition joint
__device__ float gEP[ELT];   // prior N(0,I) (degenerate in x)
__device__ float gEI[ELT];   // eInit = compose(gEP, gEG)
__device__ float gFin[ELT];  // final element

// ---------------- Tvar = tcho^T @ tcho (one block) ----------------
__global__ void __launch_bounds__(NT) prek_kernel(const float* __restrict__ tcho) {
    extern __shared__ float s[];   // 128*128
    int tid = threadIdx.x;
    for (int i = tid; i < 128 * 128; i += NT) s[i] = tcho[i];
    __syncthreads();
    int i0 = (tid >> 4) * 8, j0 = (tid & 15) * 8;
    float acc[8][8];
#pragma unroll
    for (int q = 0; q < 8; q++)
#pragma unroll
        for (int w = 0; w < 8; w++) acc[q][w] = 0.f;
    for (int k = 0; k < 128; ++k) {
        const float* row = s + (k << 7);
        float a[8], b[8];
#pragma unroll
        for (int q = 0; q < 8; q++) a[q] = row[i0 + q];
#pragma unroll
        for (int w = 0; w < 8; w++) b[w] = row[j0 + w];
#pragma unroll
        for (int q = 0; q < 8; q++)
#pragma unroll
            for (int w = 0; w < 8; w++) acc[q][w] += a[q] * b[w];
    }
#pragma unroll
    for (int q = 0; q < 8; q++)
#pragma unroll
        for (int w = 0; w < 8; w++) gTvar[(i0 + q) * 128 + j0 + w] = acc[q][w];
}

// ---------------- boundary elements ----------------
__global__ void __launch_bounds__(NT) einit_kernel(const float* __restrict__ tmu) {
    int tid = threadIdx.x;
    for (int i = tid; i < 128 * 128; i += NT) {
        gEG[SIG_OFF + i] = gTvar[i];
        int r = i >> 7, c = i & 127;
        gEP[SIG_OFF + i] = (r == c && r >= 64) ? 1.f : 0.f;
    }
    if (tid < 128) { gEG[MU_OFF + tid] = tmu[tid]; gEP[MU_OFF + tid] = 0.f; }
    if (tid == 0) { gEG[W_OFF] = 0.f; gEP[W_OFF] = 0.f; }
}

// ---------------- LDL^T factor of sS (64x64) + forward-eliminate sW (64 x ncols) ----------------
// sS full symmetric in/out; on exit diag(sS) = pivots, sW = L^{-1} * RHS.
__device__ __forceinline__ void factor_fw(float* sS, float* sW, int ncols, int tid) {
    int wid = tid >> 5, lane = tid & 31;
    for (int j = 0; j < 64; ++j) {
        float rp = __frcp_rn(sS[j * SS + j]);
        for (int i = j + 1 + wid; i < 64; i += 8) {
            float m = sS[i * SS + j] * rp;
            for (int c = lane; c < ncols; c += 32)
                sW[i * SWD + c] -= m * sW[j * SWD + c];
            for (int k = j + 1 + lane; k < 64; k += 32)
                sS[i * SS + k] -= m * sS[k * SS + j];
        }
        __syncthreads();
    }
}

// lower-triangle tile index -> (ti, tk), tk <= ti
__device__ __forceinline__ void tri_map(int m, int& ti, int& tk) {
    int t = (int)((sqrtf(8.f * (float)m + 1.f) - 1.f) * 0.5f);
    while ((t + 1) * (t + 2) / 2 <= m) ++t;
    while (t * (t + 1) / 2 > m) --t;
    ti = t; tk = m - ((t * (t + 1)) >> 1);
}

// acc[q][w] = sum_k W[k][ca+q] * inv[k] * W[k][cb+w]
__device__ __forceinline__ void wtw44(const float* sW, const float* sInv,
                                      int ca, int cb, float acc[4][4]) {
#pragma unroll
    for (int q = 0; q < 4; q++)
#pragma unroll
        for (int w = 0; w < 4; w++) acc[q][w] = 0.f;
    for (int k = 0; k < 64; ++k) {
        const float* row = sW + k * SWD;
        float iv = sInv[k];
        float4 av = *(const float4*)(row + ca);
        float4 bv = *(const float4*)(row + cb);
        float a[4] = {av.x, av.y, av.z, av.w};
        float b[4] = {bv.x * iv, bv.y * iv, bv.z * iv, bv.w * iv};
#pragma unroll
        for (int q = 0; q < 4; q++)
#pragma unroll
            for (int w = 0; w < 4; w++) acc[q][w] += a[q] * b[w];
    }
}

// ---------------- leaf: h_t = N(x; im_t, D_t) * N([x;z]; tmu, Tvar) ----------------
__global__ void __launch_bounds__(NT) leaf_kernel(const int* __restrict__ sent,
                                                  const float* __restrict__ memb,
                                                  const float* __restrict__ cemb,
                                                  const float* __restrict__ tmu) {
    extern __shared__ float sm[];
    float* sS = sm;
    float* sW = sS + 64 * SS;
    float* sInv = sW + 64 * SWD;
    float* sTv = sInv + 64;
    float* sRed = sTv + 64;
    int t = blockIdx.x, tid = threadIdx.x;
    int tok = sent[t];
    for (int idx = tid; idx < 64 * 128; idx += NT) {
        int r = idx >> 7, c = idx & 127;
        float v = gTvar[r * 128 + c];
        sW[r * SWD + c] = v;          // P_{x,:} = Tvar rows 0..63
        if (c < 64) sS[r * SS + c] = v;   // Saa
    }
    __syncthreads();
    if (tid < 64) {
        float ch = cemb[tok * 64 + tid];
        sS[tid * SS + tid] += ch * ch;                     // S = Saa + D
        sW[tid * SWD + 128] = memb[tok * 64 + tid] - tmu[tid];  // d = im - mu_a
    }
    __syncthreads();
    factor_fw(sS, sW, 129, tid);
    float val = 0.f;
    if (tid < 64) {
        float piv = sS[tid * SS + tid];
        float iv = 1.0f / piv;
        sInv[tid] = iv;
        float y = sW[tid * SWD + 128];
        sTv[tid] = y * iv;
        val = logf(piv) + y * y * iv;
    }
    for (int o = 16; o > 0; o >>= 1) val += __shfl_down_sync(~0u, val, o);
    if (tid == 0) sRed[0] = val;
    if (tid == 32) sRed[1] = val;
    __syncthreads();
    float* eo = gBufA + (size_t)t * ELT;
    if (tid < 128) {      // mu' = tmu + W^T D^-1 y   (d = im - mu_a)
        float a = 0.f;
        for (int k = 0; k < 64; ++k) a += sW[k * SWD + tid] * sTv[k];
        eo[MU_OFF + tid] = tmu[tid] + a;
    }
    if (tid == 128) eo[W_OFF] = -0.5f * (64.f * LOG2PI + sRed[0] + sRed[1]);
    // Sigma' = Tvar - W^T D^-1 W (symmetric): lower-triangle 4x4 tiles + mirror
    for (int m = tid; m < 528; m += NT) {
        int ti, tk; tri_map(m, ti, tk);
        int i0 = ti << 2, k0 = tk << 2;
        float acc[4][4];
        wtw44(sW, sInv, i0, k0, acc);
#pragma unroll
        for (int q = 0; q < 4; q++)
#pragma unroll
            for (int w = 0; w < 4; w++) {
                float vv = gTvar[(i0 + q) * 128 + k0 + w] - acc[q][w];
                eo[SIG_OFF + (i0 + q) * 128 + k0 + w] = vv;
                eo[SIG_OFF + (k0 + w) * 128 + i0 + q] = vv;
            }
    }
}

// ---------------- compose: eo(x,z) = Int e1(x,y) e2(y,z) dy ----------------
__global__ void __launch_bounds__(NT) compose_kernel(const float* __restrict__ e1b,
                                                     const float* __restrict__ e2b,
                                                     float* __restrict__ eob,
                                                     long sIn, long sOut) {
    const float* e1 = e1b + (size_t)blockIdx.x * (size_t)sIn;
    const float* e2 = e2b + (size_t)blockIdx.x * (size_t)sIn;
    float* eo = eob + (size_t)blockIdx.x * (size_t)sOut;
    extern __shared__ float sm[];
    float* sS = sm;
    float* sW = sS + 64 * SS;
    float* sInv = sW + 64 * SWD;
    float* sTv = sInv + 64;
    float* sRed = sTv + 64;
    int tid = threadIdx.x;
    const float* S1 = e1 + SIG_OFF;
    const float* S2 = e2 + SIG_OFF;
    for (int idx = tid; idx < 64 * 64; idx += NT) {
        int r = idx >> 6, c = idx & 63;
        sS[r * SS + c] = S1[(64 + r) * 128 + 64 + c] + S2[r * 128 + c];  // P_yy + Q_yy
        sW[r * SWD + c] = S1[(64 + r) * 128 + c];                         // P_yx
        sW[r * SWD + 64 + c] = S2[r * 128 + 64 + c];                      // Q_yz
    }
    if (tid < 64) sW[tid * SWD + 128] = e1[MU_OFF + 64 + tid] - e2[MU_OFF + tid];  // d = m1_y - m2_y
    __syncthreads();
    factor_fw(sS, sW, 129, tid);
    float val = 0.f;
    if (tid < 64) {
        float piv = sS[tid * SS + tid];
        float iv = 1.0f / piv;
        sInv[tid] = iv;
        float y = sW[tid * SWD + 128];
        sTv[tid] = y * iv;
        val = logf(piv) + y * y * iv;
    }
    for (int o = 16; o > 0; o >>= 1) val += __shfl_down_sync(~0u, val, o);
    if (tid == 0) sRed[0] = val;
    if (tid == 32) sRed[1] = val;
    __syncthreads();
    if (tid < 64) {        // mu'_x = m1_x - W_P^T D^-1 y
        float a = 0.f;
        for (int k = 0; k < 64; ++k) a += sW[k * SWD + tid] * sTv[k];
        eo[MU_OFF + tid] = e1[MU_OFF + tid] - a;
    } else if (tid < 128) { // mu'_z = m2_z + W_Q^T D^-1 y
        int c = tid - 64;
        float a = 0.f;
        for (int k = 0; k < 64; ++k) a += sW[k * SWD + 64 + c] * sTv[k];
        eo[MU_OFF + tid] = e2[MU_OFF + 64 + c] + a;
    }
    if (tid == 128)
        eo[W_OFF] = e1[W_OFF] + e2[W_OFF] - 0.5f * (64.f * LOG2PI + sRed[0] + sRed[1]);
    // Sigma': xx lower(136) | zz lower(136) | xz full(256)
    for (int m = tid; m < 528; m += NT) {
        float acc[4][4];
        if (m < 136) {
            int ti, tk; tri_map(m, ti, tk);
            int i0 = ti << 2, k0 = tk << 2;
            wtw44(sW, sInv, i0, k0, acc);
#pragma unroll
            for (int q = 0; q < 4; q++)
#pragma unroll
                for (int w = 0; w < 4; w++) {
                    float vv = S1[(i0 + q) * 128 + k0 + w] - acc[q][w];
                    eo[SIG_OFF + (i0 + q) * 128 + k0 + w] = vv;
                    eo[SIG_OFF + (k0 + w) * 128 + i0 + q] = vv;
                }
        } else if (m < 272) {
            int ti, tk; tri_map(m - 136, ti, tk);
            int i0 = ti << 2, k0 = tk << 2;
            wtw44(sW, sInv, 64 + i0, 64 + k0, acc);
#pragma unroll
            for (int q = 0; q < 4; q++)
#pragma unroll
                for (int w = 0; w < 4; w++) {
                    float vv = S2[(64 + i0 + q) * 128 + 64 + k0 + w] - acc[q][w];
                    eo[SIG_OFF + (64 + i0 + q) * 128 + 64 + k0 + w] = vv;
                    eo[SIG_OFF + (64 + k0 + w) * 128 + 64 + i0 + q] = vv;
                }
        } else {
            int mm = m - 272;
            int i0 = (mm >> 4) << 2, k0 = (mm & 15) << 2;
            wtw44(sW, sInv, i0, 64 + k0, acc);
#pragma unroll
            for (int q = 0; q < 4; q++)
#pragma unroll
                for (int w = 0; w < 4; w++) {
                    float vv = acc[q][w];   // Sigma'_xz = +W_P^T D^-1 W_Q
                    eo[SIG_OFF + (i0 + q) * 128 + 64 + k0 + w] = vv;
                    eo[SIG_OFF + (64 + k0 + w) * 128 + i0 + q] = vv;
                }
        }
    }
}

// ---------------- decode: 50 independent 64x64 LDL scores off gFin ----------------
__global__ void __launch_bounds__(64) decode_kernel(const float* __restrict__ omu,
                                                    const float* __restrict__ ocho,
                                                    float* __restrict__ out, int nlab) {
    __shared__ float A[64 * SS];
    __shared__ float z[64];
    __shared__ float red[2];
    int l = blockIdx.x;
    if (l >= nlab) return;
    int i = threadIdx.x;
    for (int k = 0; k <= i; ++k)
        A[i * SS + k] = gFin[SIG_OFF + (64 + i) * 128 + 64 + k];
    float oc = ocho[l * 64 + i];
    A[i * SS + i] += oc * oc;
    z[i] = gFin[MU_OFF + 64 + i] - omu[l * 64 + i];
    __syncthreads();
    float acc = 0.f;
    for (int j = 0; j < 64; ++j) {
        float piv = A[j * SS + j];
        float rp = __frcp_rn(piv);
        if (i == j) acc = logf(piv) + z[j] * z[j] * rp;
        if (i > j) {
            float mij = A[i * SS + j];
            z[i] -= mij * (z[j] * rp);
            float mjr = mij * rp;
            for (int k = j + 1; k <= i; ++k) A[i * SS + k] -= mjr * A[k * SS + j];
        }
        __syncthreads();
    }
    for (int o = 16; o > 0; o >>= 1) acc += __shfl_down_sync(0xffffffffu, acc, o);
    if ((i & 31) == 0) red[i >> 5] = acc;
    __syncthreads();
    if (i == 0) out[l] = gFin[W_OFF] - 0.5f * (64.f * LOG2PI + red[0] + red[1]);
}

// ---------------- launch ----------------
static const int CSM = (64 * SS + 64 * SWD + 64 + 64 + 8) * 4;

extern "C" void kernel_launch(void* const* d_in, const int* in_sizes, int n_in,
                              void* d_out, int out_size) {
    const int*   sent = (const int*)d_in[0];
    const float* memb = (const float*)d_in[2];
    const float* cemb = (const float*)d_in[3];
    const float* tmu  = (const float*)d_in[4];
    const float* tcho = (const float*)d_in[5];
    const float* omu  = (const float*)d_in[6];
    const float* ocho = (const float*)d_in[7];
    float* out = (float*)d_out;

    int n = in_sizes[0];
    if (n > TMAX) n = TMAX;
    if (n < 1) n = 1;
    int nlab = out_size;
    if (nlab <= 0) nlab = in_sizes[6] / 64;

    cudaFuncSetAttribute(prek_kernel, cudaFuncAttributeMaxDynamicSharedMemorySize, 128 * 128 * 4);
    cudaFuncSetAttribute(leaf_kernel, cudaFuncAttributeMaxDynamicSharedMemorySize, CSM);
    cudaFuncSetAttribute(compose_kernel, cudaFuncAttributeMaxDynamicSharedMemorySize, CSM);

    float *bufA, *bufB, *eP, *eG, *eI, *fin;
    cudaGetSymbolAddress((void**)&bufA, gBufA);
    cudaGetSymbolAddress((void**)&bufB, gBufB);
    cudaGetSymbolAddress((void**)&eP, gEP);
    cudaGetSymbolAddress((void**)&eG, gEG);
    cudaGetSymbolAddress((void**)&eI, gEI);
    cudaGetSymbolAddress((void**)&fin, gFin);

    prek_kernel<<<1, NT, 128 * 128 * 4>>>(tcho);
    einit_kernel<<<1, NT>>>(tmu);
    compose_kernel<<<1, NT, CSM>>>(eP, eG, eI, 0, 0);          // eInit = prior (.) joint
    leaf_kernel<<<n, NT, CSM>>>(sent, memb, cemb, tmu);

    float* src = bufA;
    float* dst = bufB;
    int m = n;
    while (m > 1) {
        int nc = m >> 1;
        compose_kernel<<<nc, NT, CSM>>>(src, src + ELT, dst, (long)(2 * ELT), (long)ELT);
        if (m & 1)
            cudaMemcpyAsync(dst + (size_t)nc * ELT, src + (size_t)(m - 1) * ELT,
                            (size_t)ELT * sizeof(float), cudaMemcpyDeviceToDevice);
        m = (m + 1) >> 1;
        float* tp = src; src = dst; dst = tp;
    }
    compose_kernel<<<1, NT, CSM>>>(eI, src, fin, 0, 0);
    decode_kernel<<<nlab, 64>>>(omu, ocho, out, nlab);
}

// round 8
// speedup vs baseline: 56.8307x; 1.0862x over previous
#include <cuda_runtime.h>
#include <math.h>

#define TMAX 2048
// element layout (floats): mu[0..127], logw at 128, pad to 136, Sigma 128x128
#define ELT 16520
#define MU_OFF 0
#define W_OFF 128
#define SIG_OFF 136
#define SS 65           // stride of 64x64 smem S block
#define SWD 132         // stride of 64x129 smem W block (mult of 4 -> float4 ok)
#define NT 256
#define LOG2PI 1.8378770664093453f

// ---------------- device scratch (static; no allocations) ----------------
__device__ float gTvar[128 * 128];
__device__ float gBufA[(size_t)TMAX * ELT];
__device__ float gBufB[(size_t)(TMAX / 2) * ELT];
__device__ float gEG[ELT];   // bare transition joint
__device__ float gEP[ELT];   // prior N(0,I) (degenerate in x)
__device__ float gEI[ELT];   // eInit = compose(gEP, gEG)
__device__ float gFin[ELT];  // final element

// ---------------- Tvar = tcho^T @ tcho (one block) ----------------
__global__ void __launch_bounds__(NT) prek_kernel(const float* __restrict__ tcho) {
    extern __shared__ float s[];   // 128*128
    int tid = threadIdx.x;
    for (int i = tid; i < 128 * 128; i += NT) s[i] = tcho[i];
    __syncthreads();
    int i0 = (tid >> 4) * 8, j0 = (tid & 15) * 8;
    float acc[8][8];
#pragma unroll
    for (int q = 0; q < 8; q++)
#pragma unroll
        for (int w = 0; w < 8; w++) acc[q][w] = 0.f;
    for (int k = 0; k < 128; ++k) {
        const float* row = s + (k << 7);
        float a[8], b[8];
#pragma unroll
        for (int q = 0; q < 8; q++) a[q] = row[i0 + q];
#pragma unroll
        for (int w = 0; w < 8; w++) b[w] = row[j0 + w];
#pragma unroll
        for (int q = 0; q < 8; q++)
#pragma unroll
            for (int w = 0; w < 8; w++) acc[q][w] += a[q] * b[w];
    }
#pragma unroll
    for (int q = 0; q < 8; q++)
#pragma unroll
        for (int w = 0; w < 8; w++) gTvar[(i0 + q) * 128 + j0 + w] = acc[q][w];
}

// ---------------- boundary elements ----------------
__global__ void __launch_bounds__(NT) einit_kernel(const float* __restrict__ tmu) {
    int tid = threadIdx.x;
    for (int i = tid; i < 128 * 128; i += NT) {
        gEG[SIG_OFF + i] = gTvar[i];
        int r = i >> 7, c = i & 127;
        gEP[SIG_OFF + i] = (r == c && r >= 64) ? 1.f : 0.f;
    }
    if (tid < 128) { gEG[MU_OFF + tid] = tmu[tid]; gEP[MU_OFF + tid] = 0.f; }
    if (tid == 0) { gEG[W_OFF] = 0.f; gEP[W_OFF] = 0.f; }
}

// ---------------- LDL^T factor of sS (64x64) + forward-eliminate sW (64 x ncols) ----------------
// sS full symmetric in/out; on exit diag(sS) = pivots, sW = L^{-1} * RHS.
__device__ __forceinline__ void factor_fw(float* sS, float* sW, int ncols, int tid) {
    int wid = tid >> 5, lane = tid & 31;
    for (int j = 0; j < 64; ++j) {
        float rp = __frcp_rn(sS[j * SS + j]);
        for (int i = j + 1 + wid; i < 64; i += 8) {
            float m = sS[i * SS + j] * rp;
            for (int c = lane; c < ncols; c += 32)
                sW[i * SWD + c] -= m * sW[j * SWD + c];
            for (int k = j + 1 + lane; k < 64; k += 32)
                sS[i * SS + k] -= m * sS[k * SS + j];
        }
        __syncthreads();
    }
}

// ---------------- shared epilogue: pivots -> inv, scaled RHS, score pieces ----------------
__device__ __forceinline__ void pivot_epilogue(const float* sS, const float* sW,
                                               float* sInv, float* sTv, float* sRed,
                                               int tid) {
    float val = 0.f;
    if (tid < 64) {
        float piv = sS[tid * SS + tid];
        float iv = 1.0f / piv;
        sInv[tid] = iv;
        float y = sW[tid * SWD + 128];
        sTv[tid] = y * iv;
        val = logf(piv) + y * y * iv;
    }
    for (int o = 16; o > 0; o >>= 1) val += __shfl_down_sync(~0u, val, o);
    if (tid == 0) sRed[0] = val;
    if (tid == 32) sRed[1] = val;
}

// ---------------- leaf: h_t = N(x; im_t, D_t) * N([x;z]; tmu, Tvar) ----------------
__global__ void __launch_bounds__(NT) leaf_kernel(const int* __restrict__ sent,
                                                  const float* __restrict__ memb,
                                                  const float* __restrict__ cemb,
                                                  const float* __restrict__ tmu) {
    extern __shared__ float sm[];
    float* sS = sm;
    float* sW = sS + 64 * SS;
    float* sInv = sW + 64 * SWD;
    float* sTv = sInv + 64;
    float* sRed = sTv + 64;
    int t = blockIdx.x, tid = threadIdx.x;
    int wid = tid >> 5, lane = tid & 31;
    int tok = sent[t];
    for (int idx = tid; idx < 64 * 128; idx += NT) {
        int r = idx >> 7, c = idx & 127;
        float v = gTvar[r * 128 + c];
        sW[r * SWD + c] = v;              // P_{x,:} = Tvar rows 0..63
        if (c < 64) sS[r * SS + c] = v;   // Saa
    }
    __syncthreads();
    if (tid < 64) {
        float ch = cemb[tok * 64 + tid];
        sS[tid * SS + tid] += ch * ch;                          // S = Saa + D
        sW[tid * SWD + 128] = memb[tok * 64 + tid] - tmu[tid];  // d = im - mu_a
    }
    __syncthreads();
    factor_fw(sS, sW, 129, tid);
    pivot_epilogue(sS, sW, sInv, sTv, sRed, tid);
    __syncthreads();
    float* eo = gBufA + (size_t)t * ELT;
    if (tid < 128) {      // mu' = tmu + W^T D^-1 y
        float a = 0.f;
        for (int k = 0; k < 64; ++k) a += sW[k * SWD + tid] * sTv[k];
        eo[MU_OFF + tid] = tmu[tid] + a;
    }
    if (tid == 128) eo[W_OFF] = -0.5f * (64.f * LOG2PI + sRed[0] + sRed[1]);

    // Sigma' = Tvar - W^T D^-1 W  — full 128x128, warp-row-block, coalesced
    int c = lane << 2;   // this lane's 4 output columns
#pragma unroll
    for (int pass = 0; pass < 2; ++pass) {
        int i0 = pass * 64 + wid * 8;
        float acc[8][4];
#pragma unroll
        for (int q = 0; q < 8; q++)
#pragma unroll
            for (int w = 0; w < 4; w++) acc[q][w] = 0.f;
        for (int k = 0; k < 64; ++k) {
            const float* row = sW + k * SWD;
            float iv = sInv[k];
            float4 bv = *(const float4*)(row + c);
            float b[4] = {bv.x * iv, bv.y * iv, bv.z * iv, bv.w * iv};
            float4 a0 = *(const float4*)(row + i0);
            float4 a1 = *(const float4*)(row + i0 + 4);
            float a[8] = {a0.x, a0.y, a0.z, a0.w, a1.x, a1.y, a1.z, a1.w};
#pragma unroll
            for (int q = 0; q < 8; q++)
#pragma unroll
                for (int w = 0; w < 4; w++) acc[q][w] += a[q] * b[w];
        }
#pragma unroll
        for (int q = 0; q < 8; q++) {
            int r = i0 + q;
            float4 base = *(const float4*)(gTvar + r * 128 + c);
            float4 vv;
            vv.x = base.x - acc[q][0];
            vv.y = base.y - acc[q][1];
            vv.z = base.z - acc[q][2];
            vv.w = base.w - acc[q][3];
            *(float4*)(eo + SIG_OFF + r * 128 + c) = vv;
        }
    }
}

// ---------------- compose: eo(x,z) = Int e1(x,y) e2(y,z) dy ----------------
__global__ void __launch_bounds__(NT) compose_kernel(const float* __restrict__ e1b,
                                                     const float* __restrict__ e2b,
                                                     float* __restrict__ eob,
                                                     long sIn, long sOut) {
    const float* e1 = e1b + (size_t)blockIdx.x * (size_t)sIn;
    const float* e2 = e2b + (size_t)blockIdx.x * (size_t)sIn;
    float* eo = eob + (size_t)blockIdx.x * (size_t)sOut;
    extern __shared__ float sm[];
    float* sS = sm;
    float* sW = sS + 64 * SS;
    float* sInv = sW + 64 * SWD;
    float* sTv = sInv + 64;
    float* sRed = sTv + 64;
    int tid = threadIdx.x;
    int wid = tid >> 5, lane = tid & 31;
    const float* S1 = e1 + SIG_OFF;
    const float* S2 = e2 + SIG_OFF;
    for (int idx = tid; idx < 64 * 64; idx += NT) {
        int r = idx >> 6, c = idx & 63;
        sS[r * SS + c] = S1[(64 + r) * 128 + 64 + c] + S2[r * 128 + c];  // P_yy + Q_yy
        sW[r * SWD + c] = S1[(64 + r) * 128 + c];                         // P_yx
        sW[r * SWD + 64 + c] = S2[r * 128 + 64 + c];                      // Q_yz
    }
    if (tid < 64) sW[tid * SWD + 128] = e1[MU_OFF + 64 + tid] - e2[MU_OFF + tid];  // d = m1_y - m2_y
    __syncthreads();
    factor_fw(sS, sW, 129, tid);
    pivot_epilogue(sS, sW, sInv, sTv, sRed, tid);
    __syncthreads();
    if (tid < 64) {        // mu'_x = m1_x - W_P^T D^-1 y
        float a = 0.f;
        for (int k = 0; k < 64; ++k) a += sW[k * SWD + tid] * sTv[k];
        eo[MU_OFF + tid] = e1[MU_OFF + tid] - a;
    } else if (tid < 128) { // mu'_z = m2_z + W_Q^T D^-1 y
        int cc = tid - 64;
        float a = 0.f;
        for (int k = 0; k < 64; ++k) a += sW[k * SWD + 64 + cc] * sTv[k];
        eo[MU_OFF + tid] = e2[MU_OFF + 64 + cc] + a;
    }
    if (tid == 128)
        eo[W_OFF] = e1[W_OFF] + e2[W_OFF] - 0.5f * (64.f * LOG2PI + sRed[0] + sRed[1]);

    // Sigma' full 128x128:
    //   [0:64,0:64)   = S1_xx - Wp^T D^-1 Wp
    //   [64:,64:)     = S2_zz - Wq^T D^-1 Wq
    //   cross blocks  = +W^T D^-1 W entries (exact symmetric)
    int c = lane << 2;
#pragma unroll
    for (int pass = 0; pass < 2; ++pass) {
        int i0 = pass * 64 + wid * 8;
        float acc[8][4];
#pragma unroll
        for (int q = 0; q < 8; q++)
#pragma unroll
            for (int w = 0; w < 4; w++) acc[q][w] = 0.f;
        for (int k = 0; k < 64; ++k) {
            const float* row = sW + k * SWD;
            float iv = sInv[k];
            float4 bv = *(const float4*)(row + c);
            float b[4] = {bv.x * iv, bv.y * iv, bv.z * iv, bv.w * iv};
            float4 a0 = *(const float4*)(row + i0);
            float4 a1 = *(const float4*)(row + i0 + 4);
            float a[8] = {a0.x, a0.y, a0.z, a0.w, a1.x, a1.y, a1.z, a1.w};
#pragma unroll
            for (int q = 0; q < 8; q++)
#pragma unroll
                for (int w = 0; w < 4; w++) acc[q][w] += a[q] * b[w];
        }
        bool cLow = (c < 64);
#pragma unroll
        for (int q = 0; q < 8; q++) {
            int r = i0 + q;
            float4 vv;
            if (r < 64 && cLow) {
                float4 base = *(const float4*)(S1 + r * 128 + c);
                vv.x = base.x - acc[q][0]; vv.y = base.y - acc[q][1];
                vv.z = base.z - acc[q][2]; vv.w = base.w - acc[q][3];
            } else if (r >= 64 && !cLow) {
                float4 base = *(const float4*)(S2 + r * 128 + c);
                vv.x = base.x - acc[q][0]; vv.y = base.y - acc[q][1];
                vv.z = base.z - acc[q][2]; vv.w = base.w - acc[q][3];
            } else {
                vv.x = acc[q][0]; vv.y = acc[q][1];
                vv.z = acc[q][2]; vv.w = acc[q][3];
            }
            *(float4*)(eo + SIG_OFF + r * 128 + c) = vv;
        }
    }
}

// ---------------- decode: 50 independent 64x64 LDL scores off gFin ----------------
__global__ void __launch_bounds__(64) decode_kernel(const float* __restrict__ omu,
                                                    const float* __restrict__ ocho,
                                                    float* __restrict__ out, int nlab) {
    __shared__ float A[64 * SS];
    __shared__ float z[64];
    __shared__ float red[2];
    int l = blockIdx.x;
    if (l >= nlab) return;
    int i = threadIdx.x;
    for (int k = 0; k <= i; ++k)
        A[i * SS + k] = gFin[SIG_OFF + (64 + i) * 128 + 64 + k];
    float oc = ocho[l * 64 + i];
    A[i * SS + i] += oc * oc;
    z[i] = gFin[MU_OFF + 64 + i] - omu[l * 64 + i];
    __syncthreads();
    float acc = 0.f;
    for (int j = 0; j < 64; ++j) {
        float piv = A[j * SS + j];
        float rp = __frcp_rn(piv);
        if (i == j) acc = logf(piv) + z[j] * z[j] * rp;
        if (i > j) {
            float mij = A[i * SS + j];
            z[i] -= mij * (z[j] * rp);
            float mjr = mij * rp;
            for (int k = j + 1; k <= i; ++k) A[i * SS + k] -= mjr * A[k * SS + j];
        }
        __syncthreads();
    }
    for (int o = 16; o > 0; o >>= 1) acc += __shfl_down_sync(0xffffffffu, acc, o);
    if ((i & 31) == 0) red[i >> 5] = acc;
    __syncthreads();
    if (i == 0) out[l] = gFin[W_OFF] - 0.5f * (64.f * LOG2PI + red[0] + red[1]);
}

// ---------------- launch ----------------
static const int CSM = (64 * SS + 64 * SWD + 64 + 64 + 8) * 4;

extern "C" void kernel_launch(void* const* d_in, const int* in_sizes, int n_in,
                              void* d_out, int out_size) {
    const int*   sent = (const int*)d_in[0];
    const float* memb = (const float*)d_in[2];
    const float* cemb = (const float*)d_in[3];
    const float* tmu  = (const float*)d_in[4];
    const float* tcho = (const float*)d_in[5];
    const float* omu  = (const float*)d_in[6];
    const float* ocho = (const float*)d_in[7];
    float* out = (float*)d_out;

    int n = in_sizes[0];
    if (n > TMAX) n = TMAX;
    if (n < 1) n = 1;
    int nlab = out_size;
    if (nlab <= 0) nlab = in_sizes[6] / 64;

    cudaFuncSetAttribute(prek_kernel, cudaFuncAttributeMaxDynamicSharedMemorySize, 128 * 128 * 4);
    cudaFuncSetAttribute(leaf_kernel, cudaFuncAttributeMaxDynamicSharedMemorySize, CSM);
    cudaFuncSetAttribute(compose_kernel, cudaFuncAttributeMaxDynamicSharedMemorySize, CSM);

    float *bufA, *bufB, *eP, *eG, *eI, *fin;
    cudaGetSymbolAddress((void**)&bufA, gBufA);
    cudaGetSymbolAddress((void**)&bufB, gBufB);
    cudaGetSymbolAddress((void**)&eP, gEP);
    cudaGetSymbolAddress((void**)&eG, gEG);
    cudaGetSymbolAddress((void**)&eI, gEI);
    cudaGetSymbolAddress((void**)&fin, gFin);

    prek_kernel<<<1, NT, 128 * 128 * 4>>>(tcho);
    einit_kernel<<<1, NT>>>(tmu);
    compose_kernel<<<1, NT, CSM>>>(eP, eG, eI, 0, 0);          // eInit = prior (.) joint
    leaf_kernel<<<n, NT, CSM>>>(sent, memb, cemb, tmu);

    float* src = bufA;
    float* dst = bufB;
    int m = n;
    while (m > 1) {
        int nc = m >> 1;
        compose_kernel<<<nc, NT, CSM>>>(src, src + ELT, dst, (long)(2 * ELT), (long)ELT);
        if (m & 1)
            cudaMemcpyAsync(dst + (size_t)nc * ELT, src + (size_t)(m - 1) * ELT,
                            (size_t)ELT * sizeof(float), cudaMemcpyDeviceToDevice);
        m = (m + 1) >> 1;
        float* tp = src; src = dst; dst = tp;
    }
    compose_kernel<<<1, NT, CSM>>>(eI, src, fin, 0, 0);
    decode_kernel<<<nlab, 64>>>(omu, ocho, out, nlab);
}

// round 9
// speedup vs baseline: 90.4355x; 1.5913x over previous
#include <cuda_runtime.h>
#include <math.h>

#define TMAX 2048
// element layout (floats): mu[0..127], logw at 128, pad to 136, Sigma 128x128
#define ELT 16520
#define MU_OFF 0
#define W_OFF 128
#define SIG_OFF 136
#define STR 196         // stride of fused 64x193 workspace [S(64) | W(129)] + pad
#define NG 49           // float4 groups per row (196/4)
#define D_COL 192       // RHS column (d vector)
#define NT 256
#define LOG2PI 1.8378770664093453f

// ---------------- device scratch (static; no allocations) ----------------
__device__ float gTvar[128 * 128];
__device__ float gBufA[(size_t)TMAX * ELT];
__device__ float gBufB[(size_t)(TMAX / 2) * ELT];
__device__ float gEG[ELT];   // bare transition joint
__device__ float gEP[ELT];   // prior N(0,I) (degenerate in x)
__device__ float gEI[ELT];   // eInit = compose(gEP, gEG)
__device__ float gFin[ELT];  // final element

// ---------------- Tvar = tcho^T @ tcho (one block) ----------------
__global__ void __launch_bounds__(NT) prek_kernel(const float* __restrict__ tcho) {
    extern __shared__ float s[];   // 128*128
    int tid = threadIdx.x;
    for (int i = tid; i < 128 * 128; i += NT) s[i] = tcho[i];
    __syncthreads();
    int i0 = (tid >> 4) * 8, j0 = (tid & 15) * 8;
    float acc[8][8];
#pragma unroll
    for (int q = 0; q < 8; q++)
#pragma unroll
        for (int w = 0; w < 8; w++) acc[q][w] = 0.f;
    for (int k = 0; k < 128; ++k) {
        const float* row = s + (k << 7);
        float a[8], b[8];
#pragma unroll
        for (int q = 0; q < 8; q++) a[q] = row[i0 + q];
#pragma unroll
        for (int w = 0; w < 8; w++) b[w] = row[j0 + w];
#pragma unroll
        for (int q = 0; q < 8; q++)
#pragma unroll
            for (int w = 0; w < 8; w++) acc[q][w] += a[q] * b[w];
    }
#pragma unroll
    for (int q = 0; q < 8; q++)
#pragma unroll
        for (int w = 0; w < 8; w++) gTvar[(i0 + q) * 128 + j0 + w] = acc[q][w];
}

// ---------------- boundary elements ----------------
__global__ void __launch_bounds__(NT) einit_kernel(const float* __restrict__ tmu) {
    int tid = threadIdx.x;
    for (int i = tid; i < 128 * 128; i += NT) {
        gEG[SIG_OFF + i] = gTvar[i];
        int r = i >> 7, c = i & 127;
        gEP[SIG_OFF + i] = (r == c && r >= 64) ? 1.f : 0.f;
    }
    if (tid < 128) { gEG[MU_OFF + tid] = tmu[tid]; gEP[MU_OFF + tid] = 0.f; }
    if (tid == 0) { gEG[W_OFF] = 0.f; gEP[W_OFF] = 0.f; }
}

// ---------------- blocked Gaussian elimination on fused [S | W] (64 x 193) ----------------
// On exit: diag(sA[:, :64]) = pivots, sA[:, 64:193] = L^{-1} * RHS, sInv[j] = frcp(piv_j).
__device__ __forceinline__ void factor_ge(float* sA, float* sInv, float* sL, int tid) {
#pragma unroll 1
    for (int p = 0; p < 4; ++p) {
        int c0 = p << 4;
        // ---- panel: 16 columns, 1 barrier each ----
#pragma unroll 1
        for (int jj = 0; jj < 16; ++jj) {
            int j = c0 + jj;
            float rp = __frcp_rn(sA[j * STR + j]);
            if (tid == 0) sInv[j] = rp;
            const float* rowj = sA + j * STR;
            // R1: rows (j,64) x panel cols (j, c0+16)
            int w1 = c0 + 15 - j;
            int n1 = 63 - j;
            for (int m = tid; m < n1 * w1; m += NT) {
                int i = j + 1 + m / w1;
                int k = j + 1 + m % w1;
                sA[i * STR + k] -= sA[i * STR + j] * rp * rowj[k];
            }
            // R2: panel rows (j, c0+16) x trailing col-groups [ (c0+16)/4, NG )
            int g0 = (c0 + 16) >> 2;
            int ng = NG - g0;
            for (int m = tid; m < w1 * ng; m += NT) {
                int i = j + 1 + m / ng;
                int g = g0 + m % ng;
                float mi = sA[i * STR + j] * rp;
                const float4 b = *(const float4*)(rowj + (g << 2));
                float4* dp = (float4*)(sA + i * STR + (g << 2));
                float4 a = *dp;
                a.x -= mi * b.x; a.y -= mi * b.y; a.z -= mi * b.z; a.w -= mi * b.w;
                *dp = a;
            }
            __syncthreads();
        }
        int r0 = c0 + 16;
        int nr = 64 - r0;
        if (nr == 0) break;
        // ---- scaled multipliers sL[r-r0][j] = A[r][c0+j] * inv(piv) ----
        for (int m = tid; m < nr * 16; m += NT) {
            int r = r0 + (m >> 4), jj = m & 15;
            sL[((m >> 4) << 4) + jj] = sA[r * STR + c0 + jj] * sInv[c0 + jj];
        }
        __syncthreads();
        // ---- rank-16 trailing GEMM: rows >= r0, col-groups >= r0/4 ----
        int g0 = r0 >> 2, ng = NG - g0;
        for (int m = tid; m < nr * ng; m += NT) {
            int r = r0 + m / ng;
            int g = g0 + m % ng;
            const float* lrow = sL + ((r - r0) << 4);
            float4 acc = *(const float4*)(sA + r * STR + (g << 2));
#pragma unroll
            for (int j = 0; j < 16; ++j) {
                float mlj = lrow[j];
                const float4 b = *(const float4*)(sA + (c0 + j) * STR + (g << 2));
                acc.x -= mlj * b.x; acc.y -= mlj * b.y; acc.z -= mlj * b.z; acc.w -= mlj * b.w;
            }
            *(float4*)(sA + r * STR + (g << 2)) = acc;
        }
        __syncthreads();
    }
}

// ---------------- shared epilogue: precise inv, scaled RHS, score pieces ----------------
__device__ __forceinline__ void pivot_epilogue(const float* sA, float* sInv, float* sTv,
                                               float* sRed, int tid) {
    float val = 0.f;
    if (tid < 64) {
        float piv = sA[tid * STR + tid];
        float iv = 1.0f / piv;
        sInv[tid] = iv;
        float y = sA[tid * STR + D_COL];
        sTv[tid] = y * iv;
        val = logf(piv) + y * y * iv;
    }
    for (int o = 16; o > 0; o >>= 1) val += __shfl_down_sync(~0u, val, o);
    if (tid == 0) sRed[0] = val;
    if (tid == 32) sRed[1] = val;
}

// ---------------- Schur output GEMM core: acc[8][4] for rows i0..i0+7, cols c..c+3 ----------------
__device__ __forceinline__ void schur_acc(const float* sA, const float* sInv,
                                          int i0, int c, float acc[8][4]) {
#pragma unroll
    for (int q = 0; q < 8; q++)
#pragma unroll
        for (int w = 0; w < 4; w++) acc[q][w] = 0.f;
    for (int k = 0; k < 64; ++k) {
        const float* row = sA + k * STR + 64;
        float iv = sInv[k];
        float4 bv = *(const float4*)(row + c);
        float b[4] = {bv.x * iv, bv.y * iv, bv.z * iv, bv.w * iv};
        float4 a0 = *(const float4*)(row + i0);
        float4 a1 = *(const float4*)(row + i0 + 4);
        float a[8] = {a0.x, a0.y, a0.z, a0.w, a1.x, a1.y, a1.z, a1.w};
#pragma unroll
        for (int q = 0; q < 8; q++)
#pragma unroll
            for (int w = 0; w < 4; w++) acc[q][w] += a[q] * b[w];
    }
}

// ---------------- leaf: h_t = N(x; im_t, D_t) * N([x;z]; tmu, Tvar) ----------------
__global__ void __launch_bounds__(NT) leaf_kernel(const int* __restrict__ sent,
                                                  const float* __restrict__ memb,
                                                  const float* __restrict__ cemb,
                                                  const float* __restrict__ tmu) {
    extern __shared__ float sm[];
    float* sA = sm;                 // 64 x STR
    float* sL = sA + 64 * STR;      // 48 x 16
    float* sInv = sL + 48 * 16;
    float* sTv = sInv + 64;
    float* sRed = sTv + 64;
    int t = blockIdx.x, tid = threadIdx.x;
    int wid = tid >> 5, lane = tid & 31;
    int tok = sent[t];
    for (int idx = tid; idx < 64 * 128; idx += NT) {
        int r = idx >> 7, c = idx & 127;
        float v = gTvar[r * 128 + c];
        sA[r * STR + 64 + c] = v;              // W = Tvar rows 0..63 (full 128 cols)
        if (c < 64) sA[r * STR + c] = v;       // S = Saa
    }
    __syncthreads();
    if (tid < 64) {
        float ch = cemb[tok * 64 + tid];
        sA[tid * STR + tid] += ch * ch;                         // S = Saa + D
        sA[tid * STR + D_COL] = memb[tok * 64 + tid] - tmu[tid];  // d = im - mu_a
    }
    __syncthreads();
    factor_ge(sA, sInv, sL, tid);
    pivot_epilogue(sA, sInv, sTv, sRed, tid);
    __syncthreads();
    float* eo = gBufA + (size_t)t * ELT;
    if (tid < 128) {      // mu' = tmu + W^T D^-1 y
        float a = 0.f;
        for (int k = 0; k < 64; ++k) a += sA[k * STR + 64 + tid] * sTv[k];
        eo[MU_OFF + tid] = tmu[tid] + a;
    }
    if (tid == 128) eo[W_OFF] = -0.5f * (64.f * LOG2PI + sRed[0] + sRed[1]);

    // Sigma' = Tvar - W^T D^-1 W  — full 128x128, warp-row-block, coalesced
    int c = lane << 2;
#pragma unroll
    for (int pass = 0; pass < 2; ++pass) {
        int i0 = pass * 64 + wid * 8;
        float acc[8][4];
        schur_acc(sA, sInv, i0, c, acc);
#pragma unroll
        for (int q = 0; q < 8; q++) {
            int r = i0 + q;
            float4 base = *(const float4*)(gTvar + r * 128 + c);
            float4 vv;
            vv.x = base.x - acc[q][0];
            vv.y = base.y - acc[q][1];
            vv.z = base.z - acc[q][2];
            vv.w = base.w - acc[q][3];
            *(float4*)(eo + SIG_OFF + r * 128 + c) = vv;
        }
    }
}

// ---------------- compose: eo(x,z) = Int e1(x,y) e2(y,z) dy ----------------
__global__ void __launch_bounds__(NT) compose_kernel(const float* __restrict__ e1b,
                                                     const float* __restrict__ e2b,
                                                     float* __restrict__ eob,
                                                     long sIn, long sOut) {
    const float* e1 = e1b + (size_t)blockIdx.x * (size_t)sIn;
    const float* e2 = e2b + (size_t)blockIdx.x * (size_t)sIn;
    float* eo = eob + (size_t)blockIdx.x * (size_t)sOut;
    extern __shared__ float sm[];
    float* sA = sm;
    float* sL = sA + 64 * STR;
    float* sInv = sL + 48 * 16;
    float* sTv = sInv + 64;
    float* sRed = sTv + 64;
    int tid = threadIdx.x;
    int wid = tid >> 5, lane = tid & 31;
    const float* S1 = e1 + SIG_OFF;
    const float* S2 = e2 + SIG_OFF;
    for (int idx = tid; idx < 64 * 64; idx += NT) {
        int r = idx >> 6, c = idx & 63;
        sA[r * STR + c] = S1[(64 + r) * 128 + 64 + c] + S2[r * 128 + c];  // P_yy + Q_yy
        sA[r * STR + 64 + c] = S1[(64 + r) * 128 + c];                     // P_yx
        sA[r * STR + 128 + c] = S2[r * 128 + 64 + c];                      // Q_yz
    }
    if (tid < 64) sA[tid * STR + D_COL] = e1[MU_OFF + 64 + tid] - e2[MU_OFF + tid];  // d
    __syncthreads();
    factor_ge(sA, sInv, sL, tid);
    pivot_epilogue(sA, sInv, sTv, sRed, tid);
    __syncthreads();
    if (tid < 64) {        // mu'_x = m1_x - W_P^T D^-1 y
        float a = 0.f;
        for (int k = 0; k < 64; ++k) a += sA[k * STR + 64 + tid] * sTv[k];
        eo[MU_OFF + tid] = e1[MU_OFF + tid] - a;
    } else if (tid < 128) { // mu'_z = m2_z + W_Q^T D^-1 y
        int cc = tid - 64;
        float a = 0.f;
        for (int k = 0; k < 64; ++k) a += sA[k * STR + 128 + cc] * sTv[k];
        eo[MU_OFF + tid] = e2[MU_OFF + 64 + cc] + a;
    }
    if (tid == 128)
        eo[W_OFF] = e1[W_OFF] + e2[W_OFF] - 0.5f * (64.f * LOG2PI + sRed[0] + sRed[1]);

    // Sigma' full 128x128
    int c = lane << 2;
#pragma unroll
    for (int pass = 0; pass < 2; ++pass) {
        int i0 = pass * 64 + wid * 8;
        float acc[8][4];
        schur_acc(sA, sInv, i0, c, acc);
        bool cLow = (c < 64);
#pragma unroll
        for (int q = 0; q < 8; q++) {
            int r = i0 + q;
            float4 vv;
            if (r < 64 && cLow) {
                float4 base = *(const float4*)(S1 + r * 128 + c);
                vv.x = base.x - acc[q][0]; vv.y = base.y - acc[q][1];
                vv.z = base.z - acc[q][2]; vv.w = base.w - acc[q][3];
            } else if (r >= 64 && !cLow) {
                float4 base = *(const float4*)(S2 + r * 128 + c);
                vv.x = base.x - acc[q][0]; vv.y = base.y - acc[q][1];
                vv.z = base.z - acc[q][2]; vv.w = base.w - acc[q][3];
            } else {
                vv.x = acc[q][0]; vv.y = acc[q][1];
                vv.z = acc[q][2]; vv.w = acc[q][3];
            }
            *(float4*)(eo + SIG_OFF + r * 128 + c) = vv;
        }
    }
}

// ---------------- decode: 50 independent 64x64 LDL scores off gFin ----------------
#define SSD 65
__global__ void __launch_bounds__(64) decode_kernel(const float* __restrict__ omu,
                                                    const float* __restrict__ ocho,
                                                    float* __restrict__ out, int nlab) {
    __shared__ float A[64 * SSD];
    __shared__ float z[64];
    __shared__ float red[2];
    int l = blockIdx.x;
    if (l >= nlab) return;
    int i = threadIdx.x;
    for (int k = 0; k <= i; ++k)
        A[i * SSD + k] = gFin[SIG_OFF + (64 + i) * 128 + 64 + k];
    float oc = ocho[l * 64 + i];
    A[i * SSD + i] += oc * oc;
    z[i] = gFin[MU_OFF + 64 + i] - omu[l * 64 + i];
    __syncthreads();
    float acc = 0.f;
    for (int j = 0; j < 64; ++j) {
        float piv = A[j * SSD + j];
        float rp = __frcp_rn(piv);
        if (i == j) acc = logf(piv) + z[j] * z[j] * rp;
        if (i > j) {
            float mij = A[i * SSD + j];
            z[i] -= mij * (z[j] * rp);
            float mjr = mij * rp;
            for (int k = j + 1; k <= i; ++k) A[i * SSD + k] -= mjr * A[k * SSD + j];
        }
        __syncthreads();
    }
    for (int o = 16; o > 0; o >>= 1) acc += __shfl_down_sync(0xffffffffu, acc, o);
    if ((i & 31) == 0) red[i >> 5] = acc;
    __syncthreads();
    if (i == 0) out[l] = gFin[W_OFF] - 0.5f * (64.f * LOG2PI + red[0] + red[1]);
}

// ---------------- launch ----------------
static const int CSM = (64 * STR + 48 * 16 + 64 + 64 + 8) * 4;

extern "C" void kernel_launch(void* const* d_in, const int* in_sizes, int n_in,
                              void* d_out, int out_size) {
    const int*   sent = (const int*)d_in[0];
    const float* memb = (const float*)d_in[2];
    const float* cemb = (const float*)d_in[3];
    const float* tmu  = (const float*)d_in[4];
    const float* tcho = (const float*)d_in[5];
    const float* omu  = (const float*)d_in[6];
    const float* ocho = (const float*)d_in[7];
    float* out = (float*)d_out;

    int n = in_sizes[0];
    if (n > TMAX) n = TMAX;
    if (n < 1) n = 1;
    int nlab = out_size;
    if (nlab <= 0) nlab = in_sizes[6] / 64;

    cudaFuncSetAttribute(prek_kernel, cudaFuncAttributeMaxDynamicSharedMemorySize, 128 * 128 * 4);
    cudaFuncSetAttribute(leaf_kernel, cudaFuncAttributeMaxDynamicSharedMemorySize, CSM);
    cudaFuncSetAttribute(compose_kernel, cudaFuncAttributeMaxDynamicSharedMemorySize, CSM);

    float *bufA, *bufB, *eP, *eG, *eI, *fin;
    cudaGetSymbolAddress((void**)&bufA, gBufA);
    cudaGetSymbolAddress((void**)&bufB, gBufB);
    cudaGetSymbolAddress((void**)&eP, gEP);
    cudaGetSymbolAddress((void**)&eG, gEG);
    cudaGetSymbolAddress((void**)&eI, gEI);
    cudaGetSymbolAddress((void**)&fin, gFin);

    prek_kernel<<<1, NT, 128 * 128 * 4>>>(tcho);
    einit_kernel<<<1, NT>>>(tmu);
    compose_kernel<<<1, NT, CSM>>>(eP, eG, eI, 0, 0);          // eInit = prior (.) joint
    leaf_kernel<<<n, NT, CSM>>>(sent, memb, cemb, tmu);

    float* src = bufA;
    float* dst = bufB;
    int m = n;
    while (m > 1) {
        int nc = m >> 1;
        compose_kernel<<<nc, NT, CSM>>>(src, src + ELT, dst, (long)(2 * ELT), (long)ELT);
        if (m & 1)
            cudaMemcpyAsync(dst + (size_t)nc * ELT, src + (size_t)(m - 1) * ELT,
                            (size_t)ELT * sizeof(float), cudaMemcpyDeviceToDevice);
        m = (m + 1) >> 1;
        float* tp = src; src = dst; dst = tp;
    }
    compose_kernel<<<1, NT, CSM>>>(eI, src, fin, 0, 0);
    decode_kernel<<<nlab, 64>>>(omu, ocho, out, nlab);
}

// round 11
// speedup vs baseline: 115.1185x; 1.2729x over previous
#include <cuda_runtime.h>
#include <math.h>

#define TMAX 2048
// element layout (floats): mu[0..127], logw at 128, pad to 136, Sigma 128x128
#define ELT 16520
#define MU_OFF 0
#define W_OFF 128
#define SIG_OFF 136
#define STR 196         // stride of fused 64x193 workspace [S(64) | W(128) | d(1)] + pad
#define D_COL 192       // RHS column (d vector)
#define STS 184         // stride of staging buffer rows (>= 180 floats = 45 groups)
#define NT 256
#define LOG2PI 1.8378770664093453f

// ---------------- device scratch (static; no allocations) ----------------
__device__ float gTvar[128 * 128];
__device__ float gBufA[(size_t)TMAX * ELT];
__device__ float gBufB[(size_t)(TMAX / 2) * ELT];
__device__ float gEG[ELT];   // bare transition joint
__device__ float gEP[ELT];   // prior N(0,I) (degenerate in x)
__device__ float gEI[ELT];   // eInit = compose(gEP, gEG)
__device__ float gFin[ELT];  // final element

// ---------------- Tvar = tcho^T @ tcho (one block) ----------------
__global__ void __launch_bounds__(NT) prek_kernel(const float* __restrict__ tcho) {
    extern __shared__ float s[];   // 128*128
    int tid = threadIdx.x;
    for (int i = tid; i < 128 * 128; i += NT) s[i] = tcho[i];
    __syncthreads();
    int i0 = (tid >> 4) * 8, j0 = (tid & 15) * 8;
    float acc[8][8];
#pragma unroll
    for (int q = 0; q < 8; q++)
#pragma unroll
        for (int w = 0; w < 8; w++) acc[q][w] = 0.f;
    for (int k = 0; k < 128; ++k) {
        const float* row = s + (k << 7);
        float a[8], b[8];
#pragma unroll
        for (int q = 0; q < 8; q++) a[q] = row[i0 + q];
#pragma unroll
        for (int w = 0; w < 8; w++) b[w] = row[j0 + w];
#pragma unroll
        for (int q = 0; q < 8; q++)
#pragma unroll
            for (int w = 0; w < 8; w++) acc[q][w] += a[q] * b[w];
    }
#pragma unroll
    for (int q = 0; q < 8; q++)
#pragma unroll
        for (int w = 0; w < 8; w++) gTvar[(i0 + q) * 128 + j0 + w] = acc[q][w];
}

// ---------------- boundary elements ----------------
__global__ void __launch_bounds__(NT) einit_kernel(const float* __restrict__ tmu) {
    int tid = threadIdx.x;
    for (int i = tid; i < 128 * 128; i += NT) {
        gEG[SIG_OFF + i] = gTvar[i];
        int r = i >> 7, c = i & 127;
        gEP[SIG_OFF + i] = (r == c && r >= 64) ? 1.f : 0.f;
    }
    if (tid < 128) { gEG[MU_OFF + tid] = tmu[tid]; gEP[MU_OFF + tid] = 0.f; }
    if (tid == 0) { gEG[W_OFF] = 0.f; gEP[W_OFF] = 0.f; }
}

// ---------------- fast blocked LU on fused [S | RHS] (64 x NCOLS) ----------------
// Right-looking, panel=16. Warp 0 factors each 64x16 panel in registers
// (warp-sync, scaled multipliers stored below diag, U on/above), builds
// L11^{-1} explicitly; TRSM becomes GEMM. Other warps stage panel-row
// trailing data concurrently. On exit: diag = pivots, cols of RHS hold
// L^{-1} * RHS.
template<int STRIDE, int NCOLS>
__device__ __forceinline__ void factor_fast(float* sA, float* sL11inv, float* sT, int tid) {
    const int gTot = (NCOLS + 3) >> 2;
    int wid = tid >> 5, lane = tid & 31;
#pragma unroll 1
    for (int p = 0; p < 4; ++p) {
        int c0 = p << 4;
        int g0 = (c0 + 16) >> 2;
        int tw = gTot - g0;
        if (wid == 0) {
            // ---- panel factorization in registers (warp-sync) ----
            int nrp = 64 - c0;
            int r0 = c0 + lane, r1 = r0 + 32;
            bool h0 = lane < nrp, h1 = lane + 32 < nrp;
            float a0[16], a1[16];
#pragma unroll
            for (int k = 0; k < 16; ++k) {
                a0[k] = h0 ? sA[r0 * STRIDE + c0 + k] : 0.f;
                a1[k] = h1 ? sA[r1 * STRIDE + c0 + k] : 0.f;
            }
#pragma unroll
            for (int jj = 0; jj < 16; ++jj) {
                float bk[16];
#pragma unroll
                for (int k = 0; k < 16; ++k) bk[k] = __shfl_sync(~0u, a0[k], jj);
                float rp = __frcp_rn(bk[jj]);
                if (h0 && lane > jj) {
                    float m = a0[jj] * rp; a0[jj] = m;
#pragma unroll
                    for (int k = 0; k < 16; ++k) if (k > jj) a0[k] -= m * bk[k];
                }
                if (h1) {
                    float m = a1[jj] * rp; a1[jj] = m;
#pragma unroll
                    for (int k = 0; k < 16; ++k) if (k > jj) a1[k] -= m * bk[k];
                }
            }
#pragma unroll
            for (int k = 0; k < 16; ++k) {
                if (h0) sA[r0 * STRIDE + c0 + k] = a0[k];
                if (h1) sA[r1 * STRIDE + c0 + k] = a1[k];
            }
            __syncwarp();
            // ---- explicit L11^{-1} (unit-lower, multipliers in sA) ----
            if (lane < 16) {
                int c = lane;
                float x[16];
#pragma unroll
                for (int j = 0; j < 16; ++j) {
                    float s = 0.f;
#pragma unroll
                    for (int k = 0; k < 16; ++k)
                        if (k < j) s += sA[(c0 + j) * STRIDE + c0 + k] * x[k];
                    x[j] = (j == c) ? 1.f : ((j < c) ? 0.f : -s);
                }
#pragma unroll
                for (int j = 0; j < 16; ++j) sL11inv[j * 16 + c] = x[j];
            }
        } else {
            // ---- stage panel-row trailing data (disjoint from warp 0's writes) ----
            for (int m = tid - 32; m < 16 * tw; m += (NT - 32)) {
                int i = m / tw, gg = m - i * tw;
                *(float4*)(sT + i * STS + (gg << 2)) =
                    *(const float4*)(sA + (c0 + i) * STRIDE + ((g0 + gg) << 2));
            }
        }
        __syncthreads();
        // ---- GEMM1 (TRSM): U12 = L11inv @ staged A12 ----
        for (int m = tid; m < 16 * tw; m += NT) {
            int i = m / tw, gg = m - i * tw;
            float4 acc = {0.f, 0.f, 0.f, 0.f};
#pragma unroll
            for (int k = 0; k < 16; ++k) {
                float f = sL11inv[i * 16 + k];
                const float4 b = *(const float4*)(sT + k * STS + (gg << 2));
                acc.x += f * b.x; acc.y += f * b.y; acc.z += f * b.z; acc.w += f * b.w;
            }
            *(float4*)(sA + (c0 + i) * STRIDE + ((g0 + gg) << 2)) = acc;
        }
        __syncthreads();
        // ---- GEMM2: A22 -= L21 @ U12 (rank 16) ----
        int rs = c0 + 16, nr = 64 - rs;
        for (int m = tid; m < nr * tw; m += NT) {
            int q = m / tw, gg = m - q * tw;
            int r = rs + q;
            float4 acc = *(const float4*)(sA + r * STRIDE + ((g0 + gg) << 2));
#pragma unroll
            for (int k = 0; k < 16; ++k) {
                float f = sA[r * STRIDE + c0 + k];
                const float4 b = *(const float4*)(sA + (c0 + k) * STRIDE + ((g0 + gg) << 2));
                acc.x -= f * b.x; acc.y -= f * b.y; acc.z -= f * b.z; acc.w -= f * b.w;
            }
            *(float4*)(sA + r * STRIDE + ((g0 + gg) << 2)) = acc;
        }
        __syncthreads();
    }
}

// ---------------- shared epilogue: precise inv, scaled RHS, score pieces ----------------
__device__ __forceinline__ void pivot_epilogue(const float* sA, float* sInv, float* sTv,
                                               float* sRed, int tid) {
    float val = 0.f;
    if (tid < 64) {
        float piv = sA[tid * STR + tid];
        float iv = 1.0f / piv;
        sInv[tid] = iv;
        float y = sA[tid * STR + D_COL];
        sTv[tid] = y * iv;
        val = logf(piv) + y * y * iv;
    }
    for (int o = 16; o > 0; o >>= 1) val += __shfl_down_sync(~0u, val, o);
    if (tid == 0) sRed[0] = val;
    if (tid == 32) sRed[1] = val;
}

// ---------------- Schur output GEMM core: acc[8][4] for rows i0..i0+7, cols c..c+3 ----------------
__device__ __forceinline__ void schur_acc(const float* sA, const float* sInv,
                                          int i0, int c, float acc[8][4]) {
#pragma unroll
    for (int q = 0; q < 8; q++)
#pragma unroll
        for (int w = 0; w < 4; w++) acc[q][w] = 0.f;
    for (int k = 0; k < 64; ++k) {
        const float* row = sA + k * STR + 64;
        float iv = sInv[k];
        float4 bv = *(const float4*)(row + c);
        float b[4] = {bv.x * iv, bv.y * iv, bv.z * iv, bv.w * iv};
        float4 a0 = *(const float4*)(row + i0);
        float4 a1 = *(const float4*)(row + i0 + 4);
        float a[8] = {a0.x, a0.y, a0.z, a0.w, a1.x, a1.y, a1.z, a1.w};
#pragma unroll
        for (int q = 0; q < 8; q++)
#pragma unroll
            for (int w = 0; w < 4; w++) acc[q][w] += a[q] * b[w];
    }
}

// ---------------- leaf: h_t = N(x; im_t, D_t) * N([x;z]; tmu, Tvar) ----------------
__global__ void __launch_bounds__(NT) leaf_kernel(const int* __restrict__ sent,
                                                  const float* __restrict__ memb,
                                                  const float* __restrict__ cemb,
                                                  const float* __restrict__ tmu) {
    extern __shared__ float sm[];
    float* sA = sm;                     // 64 x STR
    float* sL11inv = sA + 64 * STR;     // 16 x 16
    float* sT = sL11inv + 256;          // 16 x STS
    float* sInv = sT + 16 * STS;
    float* sTv = sInv + 64;
    float* sRed = sTv + 64;
    int t = blockIdx.x, tid = threadIdx.x;
    int wid = tid >> 5, lane = tid & 31;
    int tok = sent[t];
    for (int idx = tid; idx < 64 * 128; idx += NT) {
        int r = idx >> 7, c = idx & 127;
        float v = gTvar[r * 128 + c];
        sA[r * STR + 64 + c] = v;              // W = Tvar rows 0..63 (full 128 cols)
        if (c < 64) sA[r * STR + c] = v;       // S = Saa
    }
    __syncthreads();
    if (tid < 64) {
        float ch = cemb[tok * 64 + tid];
        sA[tid * STR + tid] += ch * ch;                           // S = Saa + D
        sA[tid * STR + D_COL] = memb[tok * 64 + tid] - tmu[tid];  // d = im - mu_a
        sA[tid * STR + 193] = 0.f; sA[tid * STR + 194] = 0.f; sA[tid * STR + 195] = 0.f;
    }
    __syncthreads();
    factor_fast<STR, 193>(sA, sL11inv, sT, tid);
    pivot_epilogue(sA, sInv, sTv, sRed, tid);
    __syncthreads();
    float* eo = gBufA + (size_t)t * ELT;
    if (tid < 128) {      // mu' = tmu + W^T D^-1 y
        float a = 0.f;
        for (int k = 0; k < 64; ++k) a += sA[k * STR + 64 + tid] * sTv[k];
        eo[MU_OFF + tid] = tmu[tid] + a;
    }
    if (tid == 128) eo[W_OFF] = -0.5f * (64.f * LOG2PI + sRed[0] + sRed[1]);

    // Sigma' = Tvar - W^T D^-1 W  — full 128x128, warp-row-block, coalesced
    int c = lane << 2;
#pragma unroll
    for (int pass = 0; pass < 2; ++pass) {
        int i0 = pass * 64 + wid * 8;
        float acc[8][4];
        schur_acc(sA, sInv, i0, c, acc);
#pragma unroll
        for (int q = 0; q < 8; q++) {
            int r = i0 + q;
            float4 base = *(const float4*)(gTvar + r * 128 + c);
            float4 vv;
            vv.x = base.x - acc[q][0];
            vv.y = base.y - acc[q][1];
            vv.z = base.z - acc[q][2];
            vv.w = base.w - acc[q][3];
            *(float4*)(eo + SIG_OFF + r * 128 + c) = vv;
        }
    }
}

// ---------------- compose: eo(x,z) = Int e1(x,y) e2(y,z) dy ----------------
__global__ void __launch_bounds__(NT) compose_kernel(const float* __restrict__ e1b,
                                                     const float* __restrict__ e2b,
                                                     float* __restrict__ eob,
                                                     long sIn, long sOut) {
    const float* e1 = e1b + (size_t)blockIdx.x * (size_t)sIn;
    const float* e2 = e2b + (size_t)blockIdx.x * (size_t)sIn;
    float* eo = eob + (size_t)blockIdx.x * (size_t)sOut;
    extern __shared__ float sm[];
    float* sA = sm;
    float* sL11inv = sA + 64 * STR;
    float* sT = sL11inv + 256;
    float* sInv = sT + 16 * STS;
    float* sTv = sInv + 64;
    float* sRed = sTv + 64;
    int tid = threadIdx.x;
    int wid = tid >> 5, lane = tid & 31;
    const float* S1 = e1 + SIG_OFF;
    const float* S2 = e2 + SIG_OFF;
    for (int idx = tid; idx < 64 * 64; idx += NT) {
        int r = idx >> 6, c = idx & 63;
        sA[r * STR + c] = S1[(64 + r) * 128 + 64 + c] + S2[r * 128 + c];  // P_yy + Q_yy
        sA[r * STR + 64 + c] = S1[(64 + r) * 128 + c];                     // P_yx
        sA[r * STR + 128 + c] = S2[r * 128 + 64 + c];                      // Q_yz
    }
    if (tid < 64) {
        sA[tid * STR + D_COL] = e1[MU_OFF + 64 + tid] - e2[MU_OFF + tid];  // d
        sA[tid * STR + 193] = 0.f; sA[tid * STR + 194] = 0.f; sA[tid * STR + 195] = 0.f;
    }
    __syncthreads();
    factor_fast<STR, 193>(sA, sL11inv, sT, tid);
    pivot_epilogue(sA, sInv, sTv, sRed, tid);
    __syncthreads();
    if (tid < 64) {        // mu'_x = m1_x - W_P^T D^-1 y
        float a = 0.f;
        for (int k = 0; k < 64; ++k) a += sA[k * STR + 64 + tid] * sTv[k];
        eo[MU_OFF + tid] = e1[MU_OFF + tid] - a;
    } else if (tid < 128) { // mu'_z = m2_z + W_Q^T D^-1 y
        int cc = tid - 64;
        float a = 0.f;
        for (int k = 0; k < 64; ++k) a += sA[k * STR + 128 + cc] * sTv[k];
        eo[MU_OFF + tid] = e2[MU_OFF + 64 + cc] + a;
    }
    if (tid == 128)
        eo[W_OFF] = e1[W_OFF] + e2[W_OFF] - 0.5f * (64.f * LOG2PI + sRed[0] + sRed[1]);

    // Sigma' full 128x128
    int c = lane << 2;
#pragma unroll
    for (int pass = 0; pass < 2; ++pass) {
        int i0 = pass * 64 + wid * 8;
        float acc[8][4];
        schur_acc(sA, sInv, i0, c, acc);
        bool cLow = (c < 64);
#pragma unroll
        for (int q = 0; q < 8; q++) {
            int r = i0 + q;
            float4 vv;
            if (r < 64 && cLow) {
                float4 base = *(const float4*)(S1 + r * 128 + c);
                vv.x = base.x - acc[q][0]; vv.y = base.y - acc[q][1];
                vv.z = base.z - acc[q][2]; vv.w = base.w - acc[q][3];
            } else if (r >= 64 && !cLow) {
                float4 base = *(const float4*)(S2 + r * 128 + c);
                vv.x = base.x - acc[q][0]; vv.y = base.y - acc[q][1];
                vv.z = base.z - acc[q][2]; vv.w = base.w - acc[q][3];
            } else {
                vv.x = acc[q][0]; vv.y = acc[q][1];
                vv.z = acc[q][2]; vv.w = acc[q][3];
            }
            *(float4*)(eo + SIG_OFF + r * 128 + c) = vv;
        }
    }
}

// ---------------- decode: 50 independent scores via the same fast factor ----------------
#define DSTR 68
__global__ void __launch_bounds__(NT) decode_kernel(const float* __restrict__ omu,
                                                    const float* __restrict__ ocho,
                                                    float* __restrict__ out, int nlab) {
    extern __shared__ float sm[];
    float* sA = sm;                    // 64 x DSTR, cols: S(64) | z(1) | pad
    float* sL11inv = sA + 64 * DSTR;
    float* sT = sL11inv + 256;
    float* sRed = sT + 16 * STS;
    int l = blockIdx.x, tid = threadIdx.x;
    if (l >= nlab) return;
    for (int idx = tid; idx < 64 * 64; idx += NT) {
        int r = idx >> 6, c = idx & 63;
        sA[r * DSTR + c] = gFin[SIG_OFF + (64 + r) * 128 + 64 + c];
    }
    __syncthreads();
    if (tid < 64) {
        float oc = ocho[l * 64 + tid];
        sA[tid * DSTR + tid] += oc * oc;
        sA[tid * DSTR + 64] = gFin[MU_OFF + 64 + tid] - omu[l * 64 + tid];
        sA[tid * DSTR + 65] = 0.f; sA[tid * DSTR + 66] = 0.f; sA[tid * DSTR + 67] = 0.f;
    }
    __syncthreads();
    factor_fast<DSTR, 65>(sA, sL11inv, sT, tid);
    float val = 0.f;
    if (tid < 64) {
        float piv = sA[tid * DSTR + tid];
        float y = sA[tid * DSTR + 64];
        val = logf(piv) + y * y / piv;
    }
    for (int o = 16; o > 0; o >>= 1) val += __shfl_down_sync(~0u, val, o);
    if (tid == 0) sRed[0] = val;
    if (tid == 32) sRed[1] = val;
    __syncthreads();
    if (tid == 0) out[l] = gFin[W_OFF] - 0.5f * (64.f * LOG2PI + sRed[0] + sRed[1]);
}

// ---------------- launch ----------------
static const int CSM = (64 * STR + 256 + 16 * STS + 64 + 64 + 8) * 4;
static const int DSM = (64 * DSTR + 256 + 16 * STS + 8) * 4;

extern "C" void kernel_launch(void* const* d_in, const int* in_sizes, int n_in,
                              void* d_out, int out_size) {
    const int*   sent = (const int*)d_in[0];
    const float* memb = (const float*)d_in[2];
    const float* cemb = (const float*)d_in[3];
    const float* tmu  = (const float*)d_in[4];
    const float* tcho = (const float*)d_in[5];
    const float* omu  = (const float*)d_in[6];
    const float* ocho = (const float*)d_in[7];
    float* out = (float*)d_out;

    int n = in_sizes[0];
    if (n > TMAX) n = TMAX;
    if (n < 1) n = 1;
    int nlab = out_size;
    if (nlab <= 0) nlab = in_sizes[6] / 64;

    cudaFuncSetAttribute(prek_kernel, cudaFuncAttributeMaxDynamicSharedMemorySize, 128 * 128 * 4);
    cudaFuncSetAttribute(leaf_kernel, cudaFuncAttributeMaxDynamicSharedMemorySize, CSM);
    cudaFuncSetAttribute(compose_kernel, cudaFuncAttributeMaxDynamicSharedMemorySize, CSM);
    cudaFuncSetAttribute(decode_kernel, cudaFuncAttributeMaxDynamicSharedMemorySize, DSM);

    float *bufA, *bufB, *eP, *eG, *eI, *fin;
    cudaGetSymbolAddress((void**)&bufA, gBufA);
    cudaGetSymbolAddress((void**)&bufB, gBufB);
    cudaGetSymbolAddress((void**)&eP, gEP);
    cudaGetSymbolAddress((void**)&eG, gEG);
    cudaGetSymbolAddress((void**)&eI, gEI);
    cudaGetSymbolAddress((void**)&fin, gFin);

    prek_kernel<<<1, NT, 128 * 128 * 4>>>(tcho);
    einit_kernel<<<1, NT>>>(tmu);
    compose_kernel<<<1, NT, CSM>>>(eP, eG, eI, 0, 0);          // eInit = prior (.) joint
    leaf_kernel<<<n, NT, CSM>>>(sent, memb, cemb, tmu);

    float* src = bufA;
    float* dst = bufB;
    int m = n;
    while (m > 1) {
        int nc = m >> 1;
        compose_kernel<<<nc, NT, CSM>>>(src, src + ELT, dst, (long)(2 * ELT), (long)ELT);
        if (m & 1)
            cudaMemcpyAsync(dst + (size_t)nc * ELT, src + (size_t)(m - 1) * ELT,
                            (size_t)ELT * sizeof(float), cudaMemcpyDeviceToDevice);
        m = (m + 1) >> 1;
        float* tp = src; src = dst; dst = tp;
    }
    compose_kernel<<<1, NT, CSM>>>(eI, src, fin, 0, 0);
    decode_kernel<<<nlab, NT, DSM>>>(omu, ocho, out, nlab);
}